// round 1
// baseline (speedup 1.0000x reference)
#include <cuda_runtime.h>

#define BS 4
#define C 128
#define L 4096     // H*W = 64*64
#define D 64       // INNER

// Scratch for q,k,v: BS*L*D floats each = 4 MB each (device globals, no alloc).
__device__ float g_q[BS * L * D];
__device__ float g_k[BS * L * D];
__device__ float g_v[BS * L * D];

// ---------------------------------------------------------------------------
// Kernel 1: QKV projection.
// x[b,l,c] = inpt[b,c,l]  (l = h*W + w), q/k/v[b,l,d] = sum_c x*W[d,c] + b[d]
// Block: 256 threads, 32 tokens per block. grid = (L/32, BS).
// ---------------------------------------------------------------------------
__global__ __launch_bounds__(256) void qkv_kernel(
    const float* __restrict__ inpt,
    const float* __restrict__ Wq, const float* __restrict__ bq,
    const float* __restrict__ Wk, const float* __restrict__ bk,
    const float* __restrict__ Wv, const float* __restrict__ bv)
{
    __shared__ float xs[C * 33];   // xs[c*33 + j], j = local token
    __shared__ float os[D * 33];   // output staging [d*33 + j]

    const int b   = blockIdx.y;
    const int l0  = blockIdx.x * 32;
    const int tid = threadIdx.x;

    // Coalesced load of x tile: inpt[b, c, l0+j], contiguous in j per c.
    const float* src = inpt + ((size_t)b * C) * L + l0;
    #pragma unroll
    for (int idx = tid; idx < C * 32; idx += 256) {
        int c = idx >> 5, j = idx & 31;
        xs[c * 33 + j] = src[(size_t)c * L + j];
    }
    __syncthreads();

    const float* Ws[3]  = {Wq, Wk, Wv};
    const float* bs_[3] = {bq, bk, bv};
    float* outs[3]      = {g_q, g_k, g_v};

    for (int mat = 0; mat < 3; mat++) {
        const float* __restrict__ Wp = Ws[mat];
        const float* __restrict__ bp = bs_[mat];

        // 2048 outputs (32 tokens x 64 dims); 8 per thread.
        // Lanes map to j (token) -> W loads are warp-uniform (broadcast LDG),
        // xs loads conflict-free (stride 33).
        float accs[8];
        #pragma unroll
        for (int k = 0; k < 8; k++) {
            int o = tid + k * 256;
            int j = o & 31, d = o >> 5;
            float a0 = bp[d], a1 = 0.f, a2 = 0.f, a3 = 0.f;
            const float4* w4 = (const float4*)(Wp + d * C);
            #pragma unroll
            for (int c4 = 0; c4 < C / 4; c4++) {
                float4 w = w4[c4];
                int c = c4 * 4;
                a0 += xs[(c + 0) * 33 + j] * w.x;
                a1 += xs[(c + 1) * 33 + j] * w.y;
                a2 += xs[(c + 2) * 33 + j] * w.z;
                a3 += xs[(c + 3) * 33 + j] * w.w;
            }
            accs[k] = (a0 + a1) + (a2 + a3);
        }
        __syncthreads();   // prior mat's os reads complete
        #pragma unroll
        for (int k = 0; k < 8; k++) {
            int o = tid + k * 256;
            int j = o & 31, d = o >> 5;
            os[d * 33 + j] = accs[k];
        }
        __syncthreads();
        // Coalesced store: lanes over d (contiguous in g layout [token][d]).
        float* op = outs[mat];
        #pragma unroll
        for (int idx = tid; idx < 2048; idx += 256) {
            int d = idx & 63, j = idx >> 6;
            op[((size_t)(b * L + l0 + j)) * D + d] = os[d * 33 + j];
        }
    }
}

// ---------------------------------------------------------------------------
// Kernel 2: flash attention + fused output projection + residual.
// One thread per query row; 32 rows per block (1 warp). grid = (L/32, BS).
// K/V tiles of 64 keys in SMEM; online softmax; ctx stays in registers;
// epilogue does ctx @ Wo^T + bo + inpt with coalesced NCHW stores.
// ---------------------------------------------------------------------------
__global__ __launch_bounds__(32) void attn_kernel(
    const float* __restrict__ inpt,
    const float* __restrict__ Wo,
    const float* __restrict__ bo,
    float* __restrict__ out)
{
    __shared__ float Ks[64 * D];    // 16 KB
    __shared__ float Vs[64 * D];    // 16 KB
    __shared__ float Ss[32 * 65];   // scores, stride 65 -> conflict-free

    const int b   = blockIdx.y;
    const int r0  = blockIdx.x * 32;
    const int tid = threadIdx.x;
    const int row = r0 + tid;

    // q row into registers
    float4 q4[16];
    {
        const float4* qp = (const float4*)(g_q + ((size_t)(b * L + row)) * D);
        #pragma unroll
        for (int i = 0; i < 16; i++) q4[i] = qp[i];
    }

    float4 acc[16];
    #pragma unroll
    for (int i = 0; i < 16; i++) acc[i] = make_float4(0.f, 0.f, 0.f, 0.f);
    float m_run = -1e30f;
    float lsum  = 0.f;
    const float inv_scale = 0.125f;   // 1 / round(sqrt(64),2) = 1/8 exactly

    float* Sr = Ss + tid * 65;

    for (int kt = 0; kt < L / 64; kt++) {
        __syncthreads();
        // load K/V tile (64 keys x 64 d), coalesced float4
        {
            const float4* kp = (const float4*)(g_k + ((size_t)(b * L + kt * 64)) * D);
            const float4* vp = (const float4*)(g_v + ((size_t)(b * L + kt * 64)) * D);
            float4* K4 = (float4*)Ks;
            float4* V4 = (float4*)Vs;
            #pragma unroll
            for (int t = 0; t < 32; t++) {
                K4[tid + t * 32] = kp[tid + t * 32];
                V4[tid + t * 32] = vp[tid + t * 32];
            }
        }
        __syncthreads();

        // scores for this thread's row
        float tmax = -1e30f;
        #pragma unroll 4
        for (int j = 0; j < 64; j++) {
            const float4* kk = (const float4*)(Ks + j * D);
            float s0 = 0.f, s1 = 0.f, s2 = 0.f, s3 = 0.f;
            #pragma unroll
            for (int i = 0; i < 16; i += 4) {
                float4 k0 = kk[i], k1 = kk[i+1], k2 = kk[i+2], k3 = kk[i+3];
                s0 += q4[i  ].x*k0.x + q4[i  ].y*k0.y + q4[i  ].z*k0.z + q4[i  ].w*k0.w;
                s1 += q4[i+1].x*k1.x + q4[i+1].y*k1.y + q4[i+1].z*k1.z + q4[i+1].w*k1.w;
                s2 += q4[i+2].x*k2.x + q4[i+2].y*k2.y + q4[i+2].z*k2.z + q4[i+2].w*k2.w;
                s3 += q4[i+3].x*k3.x + q4[i+3].y*k3.y + q4[i+3].z*k3.z + q4[i+3].w*k3.w;
            }
            float s = ((s0 + s1) + (s2 + s3)) * inv_scale;
            Sr[j] = s;
            tmax = fmaxf(tmax, s);
        }

        // online softmax rescale
        float m_new = fmaxf(m_run, tmax);
        float corr  = __expf(m_run - m_new);
        lsum *= corr;
        #pragma unroll
        for (int i = 0; i < 16; i++) {
            acc[i].x *= corr; acc[i].y *= corr; acc[i].z *= corr; acc[i].w *= corr;
        }
        m_run = m_new;

        // accumulate p @ V
        #pragma unroll 2
        for (int j = 0; j < 64; j++) {
            float p = __expf(Sr[j] - m_new);
            lsum += p;
            const float4* vv = (const float4*)(Vs + j * D);
            #pragma unroll
            for (int i = 0; i < 16; i++) {
                float4 t = vv[i];
                acc[i].x += p * t.x; acc[i].y += p * t.y;
                acc[i].z += p * t.z; acc[i].w += p * t.w;
            }
        }
    }

    // normalize ctx in registers
    float inv_l = 1.f / lsum;
    #pragma unroll
    for (int i = 0; i < 16; i++) {
        acc[i].x *= inv_l; acc[i].y *= inv_l; acc[i].z *= inv_l; acc[i].w *= inv_l;
    }

    // fused out projection + bias + residual, coalesced stores per channel
    const float4* Wo4 = (const float4*)Wo;
    const size_t base = (size_t)b * C * L + r0 + tid;
    #pragma unroll 4
    for (int c = 0; c < C; c++) {
        float v0 = 0.f, v1 = 0.f, v2 = 0.f, v3 = 0.f;
        #pragma unroll
        for (int i = 0; i < 16; i += 4) {
            float4 w0 = Wo4[c*16 + i], w1 = Wo4[c*16 + i+1],
                   w2 = Wo4[c*16 + i+2], w3 = Wo4[c*16 + i+3];
            v0 += acc[i  ].x*w0.x + acc[i  ].y*w0.y + acc[i  ].z*w0.z + acc[i  ].w*w0.w;
            v1 += acc[i+1].x*w1.x + acc[i+1].y*w1.y + acc[i+1].z*w1.z + acc[i+1].w*w1.w;
            v2 += acc[i+2].x*w2.x + acc[i+2].y*w2.y + acc[i+2].z*w2.z + acc[i+2].w*w2.w;
            v3 += acc[i+3].x*w3.x + acc[i+3].y*w3.y + acc[i+3].z*w3.z + acc[i+3].w*w3.w;
        }
        float val = bo[c] + (v0 + v1) + (v2 + v3);
        out[base + (size_t)c * L] = inpt[base + (size_t)c * L] + val;
    }
}

// ---------------------------------------------------------------------------
extern "C" void kernel_launch(void* const* d_in, const int* in_sizes, int n_in,
                              void* d_out, int out_size)
{
    const float* inpt = (const float*)d_in[0];
    const float* Wq   = (const float*)d_in[1];
    const float* bq   = (const float*)d_in[2];
    const float* Wk   = (const float*)d_in[3];
    const float* bk   = (const float*)d_in[4];
    const float* Wv   = (const float*)d_in[5];
    const float* bv   = (const float*)d_in[6];
    const float* Wo   = (const float*)d_in[7];
    const float* bo   = (const float*)d_in[8];
    float* out = (float*)d_out;

    dim3 g1(L / 32, BS);
    qkv_kernel<<<g1, 256>>>(inpt, Wq, bq, Wk, bk, Wv, bv);

    dim3 g2(L / 32, BS);
    attn_kernel<<<g2, 32>>>(inpt, Wo, bo, out);
}

// round 2
// speedup vs baseline: 1.0013x; 1.0013x over previous
#include <cuda_runtime.h>

#define BS 4
#define C 128
#define L 4096     // H*W = 64*64
#define D 64       // INNER

// Scratch for q,k,v: BS*L*D floats each = 4 MB each (device globals, no alloc).
__device__ float g_q[BS * L * D];
__device__ float g_k[BS * L * D];
__device__ float g_v[BS * L * D];

// ---------------------------------------------------------------------------
// Kernel 1: QKV projection.
// x[b,l,c] = inpt[b,c,l]  (l = h*W + w), q/k/v[b,l,d] = sum_c x*W[d,c] + b[d]
// Block: 256 threads, 32 tokens per block. grid = (L/32, BS).
// ---------------------------------------------------------------------------
__global__ __launch_bounds__(256) void qkv_kernel(
    const float* __restrict__ inpt,
    const float* __restrict__ Wq, const float* __restrict__ bq,
    const float* __restrict__ Wk, const float* __restrict__ bk,
    const float* __restrict__ Wv, const float* __restrict__ bv)
{
    __shared__ float xs[C * 33];   // xs[c*33 + j], j = local token
    __shared__ float os[D * 33];   // output staging [d*33 + j]

    const int b   = blockIdx.y;
    const int l0  = blockIdx.x * 32;
    const int tid = threadIdx.x;

    // Coalesced load of x tile: inpt[b, c, l0+j], contiguous in j per c.
    const float* src = inpt + ((size_t)b * C) * L + l0;
    #pragma unroll
    for (int idx = tid; idx < C * 32; idx += 256) {
        int c = idx >> 5, j = idx & 31;
        xs[c * 33 + j] = src[(size_t)c * L + j];
    }
    __syncthreads();

    const float* Ws[3]  = {Wq, Wk, Wv};
    const float* bs_[3] = {bq, bk, bv};
    float* outs[3]      = {g_q, g_k, g_v};

    for (int mat = 0; mat < 3; mat++) {
        const float* __restrict__ Wp = Ws[mat];
        const float* __restrict__ bp = bs_[mat];

        // 2048 outputs (32 tokens x 64 dims); 8 per thread.
        // Lanes map to j (token) -> W loads are warp-uniform (broadcast LDG),
        // xs loads conflict-free (stride 33).
        float accs[8];
        #pragma unroll
        for (int k = 0; k < 8; k++) {
            int o = tid + k * 256;
            int j = o & 31, d = o >> 5;
            float a0 = bp[d], a1 = 0.f, a2 = 0.f, a3 = 0.f;
            const float4* w4 = (const float4*)(Wp + d * C);
            #pragma unroll
            for (int c4 = 0; c4 < C / 4; c4++) {
                float4 w = w4[c4];
                int c = c4 * 4;
                a0 += xs[(c + 0) * 33 + j] * w.x;
                a1 += xs[(c + 1) * 33 + j] * w.y;
                a2 += xs[(c + 2) * 33 + j] * w.z;
                a3 += xs[(c + 3) * 33 + j] * w.w;
            }
            accs[k] = (a0 + a1) + (a2 + a3);
        }
        __syncthreads();   // prior mat's os reads complete
        #pragma unroll
        for (int k = 0; k < 8; k++) {
            int o = tid + k * 256;
            int j = o & 31, d = o >> 5;
            os[d * 33 + j] = accs[k];
        }
        __syncthreads();
        // Coalesced store: lanes over d (contiguous in g layout [token][d]).
        float* op = outs[mat];
        #pragma unroll
        for (int idx = tid; idx < 2048; idx += 256) {
            int d = idx & 63, j = idx >> 6;
            op[((size_t)(b * L + l0 + j)) * D + d] = os[d * 33 + j];
        }
    }
}

// ---------------------------------------------------------------------------
// Kernel 2: flash attention + fused output projection + residual.
// One thread per query row; 32 rows per block (1 warp). grid = (L/32, BS).
// K/V tiles of 64 keys in SMEM; online softmax; ctx stays in registers;
// epilogue does ctx @ Wo^T + bo + inpt with coalesced NCHW stores.
// ---------------------------------------------------------------------------
__global__ __launch_bounds__(32) void attn_kernel(
    const float* __restrict__ inpt,
    const float* __restrict__ Wo,
    const float* __restrict__ bo,
    float* __restrict__ out)
{
    __shared__ float Ks[64 * D];    // 16 KB
    __shared__ float Vs[64 * D];    // 16 KB
    __shared__ float Ss[32 * 65];   // scores, stride 65 -> conflict-free

    const int b   = blockIdx.y;
    const int r0  = blockIdx.x * 32;
    const int tid = threadIdx.x;
    const int row = r0 + tid;

    // q row into registers
    float4 q4[16];
    {
        const float4* qp = (const float4*)(g_q + ((size_t)(b * L + row)) * D);
        #pragma unroll
        for (int i = 0; i < 16; i++) q4[i] = qp[i];
    }

    float4 acc[16];
    #pragma unroll
    for (int i = 0; i < 16; i++) acc[i] = make_float4(0.f, 0.f, 0.f, 0.f);
    float m_run = -1e30f;
    float lsum  = 0.f;
    const float inv_scale = 0.125f;   // 1 / round(sqrt(64),2) = 1/8 exactly

    float* Sr = Ss + tid * 65;

    for (int kt = 0; kt < L / 64; kt++) {
        __syncthreads();
        // load K/V tile (64 keys x 64 d), coalesced float4
        {
            const float4* kp = (const float4*)(g_k + ((size_t)(b * L + kt * 64)) * D);
            const float4* vp = (const float4*)(g_v + ((size_t)(b * L + kt * 64)) * D);
            float4* K4 = (float4*)Ks;
            float4* V4 = (float4*)Vs;
            #pragma unroll
            for (int t = 0; t < 32; t++) {
                K4[tid + t * 32] = kp[tid + t * 32];
                V4[tid + t * 32] = vp[tid + t * 32];
            }
        }
        __syncthreads();

        // scores for this thread's row
        float tmax = -1e30f;
        #pragma unroll 4
        for (int j = 0; j < 64; j++) {
            const float4* kk = (const float4*)(Ks + j * D);
            float s0 = 0.f, s1 = 0.f, s2 = 0.f, s3 = 0.f;
            #pragma unroll
            for (int i = 0; i < 16; i += 4) {
                float4 k0 = kk[i], k1 = kk[i+1], k2 = kk[i+2], k3 = kk[i+3];
                s0 += q4[i  ].x*k0.x + q4[i  ].y*k0.y + q4[i  ].z*k0.z + q4[i  ].w*k0.w;
                s1 += q4[i+1].x*k1.x + q4[i+1].y*k1.y + q4[i+1].z*k1.z + q4[i+1].w*k1.w;
                s2 += q4[i+2].x*k2.x + q4[i+2].y*k2.y + q4[i+2].z*k2.z + q4[i+2].w*k2.w;
                s3 += q4[i+3].x*k3.x + q4[i+3].y*k3.y + q4[i+3].z*k3.z + q4[i+3].w*k3.w;
            }
            float s = ((s0 + s1) + (s2 + s3)) * inv_scale;
            Sr[j] = s;
            tmax = fmaxf(tmax, s);
        }

        // online softmax rescale
        float m_new = fmaxf(m_run, tmax);
        float corr  = __expf(m_run - m_new);
        lsum *= corr;
        #pragma unroll
        for (int i = 0; i < 16; i++) {
            acc[i].x *= corr; acc[i].y *= corr; acc[i].z *= corr; acc[i].w *= corr;
        }
        m_run = m_new;

        // accumulate p @ V
        #pragma unroll 2
        for (int j = 0; j < 64; j++) {
            float p = __expf(Sr[j] - m_new);
            lsum += p;
            const float4* vv = (const float4*)(Vs + j * D);
            #pragma unroll
            for (int i = 0; i < 16; i++) {
                float4 t = vv[i];
                acc[i].x += p * t.x; acc[i].y += p * t.y;
                acc[i].z += p * t.z; acc[i].w += p * t.w;
            }
        }
    }

    // normalize ctx in registers
    float inv_l = 1.f / lsum;
    #pragma unroll
    for (int i = 0; i < 16; i++) {
        acc[i].x *= inv_l; acc[i].y *= inv_l; acc[i].z *= inv_l; acc[i].w *= inv_l;
    }

    // fused out projection + bias + residual, coalesced stores per channel
    const float4* Wo4 = (const float4*)Wo;
    const size_t base = (size_t)b * C * L + r0 + tid;
    #pragma unroll 4
    for (int c = 0; c < C; c++) {
        float v0 = 0.f, v1 = 0.f, v2 = 0.f, v3 = 0.f;
        #pragma unroll
        for (int i = 0; i < 16; i += 4) {
            float4 w0 = Wo4[c*16 + i], w1 = Wo4[c*16 + i+1],
                   w2 = Wo4[c*16 + i+2], w3 = Wo4[c*16 + i+3];
            v0 += acc[i  ].x*w0.x + acc[i  ].y*w0.y + acc[i  ].z*w0.z + acc[i  ].w*w0.w;
            v1 += acc[i+1].x*w1.x + acc[i+1].y*w1.y + acc[i+1].z*w1.z + acc[i+1].w*w1.w;
            v2 += acc[i+2].x*w2.x + acc[i+2].y*w2.y + acc[i+2].z*w2.z + acc[i+2].w*w2.w;
            v3 += acc[i+3].x*w3.x + acc[i+3].y*w3.y + acc[i+3].z*w3.z + acc[i+3].w*w3.w;
        }
        float val = bo[c] + (v0 + v1) + (v2 + v3);
        out[base + (size_t)c * L] = inpt[base + (size_t)c * L] + val;
    }
}

// ---------------------------------------------------------------------------
extern "C" void kernel_launch(void* const* d_in, const int* in_sizes, int n_in,
                              void* d_out, int out_size)
{
    const float* inpt = (const float*)d_in[0];
    const float* Wq   = (const float*)d_in[1];
    const float* bq   = (const float*)d_in[2];
    const float* Wk   = (const float*)d_in[3];
    const float* bk   = (const float*)d_in[4];
    const float* Wv   = (const float*)d_in[5];
    const float* bv   = (const float*)d_in[6];
    const float* Wo   = (const float*)d_in[7];
    const float* bo   = (const float*)d_in[8];
    float* out = (float*)d_out;

    dim3 g1(L / 32, BS);
    qkv_kernel<<<g1, 256>>>(inpt, Wq, bq, Wk, bk, Wv, bv);

    dim3 g2(L / 32, BS);
    attn_kernel<<<g2, 32>>>(inpt, Wo, bo, out);
}

// round 4
// speedup vs baseline: 2.7785x; 2.7749x over previous
#include <cuda_runtime.h>
#include <cstdint>

#define BSZ 4
#define CCH 128
#define LL  4096
#define DDIM 64
#define BM  128
#define BN  64
#define NT  (LL/BN)

__device__ float g_q[BSZ * LL * DDIM];
__device__ float g_k[BSZ * LL * DDIM];
__device__ float g_vT[BSZ * DDIM * LL];

__device__ __forceinline__ float to_tf32(float x) {
    uint32_t r; asm("cvt.rna.tf32.f32 %0, %1;" : "=r"(r) : "f"(x));
    return __uint_as_float(r);
}
__device__ __forceinline__ float fexp2_fast(float y) {
    float z = __fadd_rn(y, 12582912.f);
    int   n = __float_as_int(z);
    float t = __fsub_rn(z, 12582912.f);
    float f = __fsub_rn(y, t);
    float p = 1.3333558146e-3f;
    p = fmaf(p, f, 9.6181291918e-3f);
    p = fmaf(p, f, 5.5504108665e-2f);
    p = fmaf(p, f, 2.4022650696e-1f);
    p = fmaf(p, f, 6.9314718056e-1f);
    p = fmaf(p, f, 1.0f);
    return __int_as_float(__float_as_int(p) + (n << 23));
}
__device__ __forceinline__ void mma8(float* c,
    uint32_t a0, uint32_t a1, uint32_t a2, uint32_t a3,
    uint32_t b0, uint32_t b1)
{
    asm volatile("mma.sync.aligned.m16n8k8.row.col.f32.tf32.tf32.f32 "
        "{%0,%1,%2,%3}, {%4,%5,%6,%7}, {%8,%9}, {%0,%1,%2,%3};"
        : "+f"(c[0]), "+f"(c[1]), "+f"(c[2]), "+f"(c[3])
        : "r"(a0), "r"(a1), "r"(a2), "r"(a3), "r"(b0), "r"(b1));
}
#define U(x) __float_as_uint(x)

// ---------------- QKV projection (tf32-rounded; v transposed) ---------------
__global__ __launch_bounds__(256) void qkv_kernel(
    const float* __restrict__ inpt,
    const float* __restrict__ Wq, const float* __restrict__ bq,
    const float* __restrict__ Wk, const float* __restrict__ bk,
    const float* __restrict__ Wv, const float* __restrict__ bv)
{
    __shared__ float xs[CCH * 33];
    __shared__ float os[DDIM * 33];
    const int b = blockIdx.y, l0 = blockIdx.x * 32, tid = threadIdx.x;

    const float* src = inpt + ((size_t)b * CCH) * LL + l0;
    #pragma unroll
    for (int idx = tid; idx < CCH * 32; idx += 256) {
        int c = idx >> 5, j = idx & 31;
        xs[c * 33 + j] = src[(size_t)c * LL + j];
    }
    __syncthreads();

    const float* Ws[3]  = {Wq, Wk, Wv};
    const float* bs_[3] = {bq, bk, bv};

    for (int mat = 0; mat < 3; mat++) {
        const float* __restrict__ Wp = Ws[mat];
        const float* __restrict__ bp = bs_[mat];
        float accs[8];
        #pragma unroll
        for (int k = 0; k < 8; k++) {
            int o = tid + k * 256;
            int j = o & 31, d = o >> 5;
            float a0 = bp[d], a1 = 0.f, a2 = 0.f, a3 = 0.f;
            const float4* w4 = (const float4*)(Wp + d * CCH);
            #pragma unroll
            for (int c4 = 0; c4 < CCH / 4; c4++) {
                float4 w = w4[c4];
                int c = c4 * 4;
                a0 += xs[(c + 0) * 33 + j] * w.x;
                a1 += xs[(c + 1) * 33 + j] * w.y;
                a2 += xs[(c + 2) * 33 + j] * w.z;
                a3 += xs[(c + 3) * 33 + j] * w.w;
            }
            accs[k] = to_tf32((a0 + a1) + (a2 + a3));
        }
        __syncthreads();
        #pragma unroll
        for (int k = 0; k < 8; k++) {
            int o = tid + k * 256;
            os[(o >> 5) * 33 + (o & 31)] = accs[k];
        }
        __syncthreads();
        if (mat < 2) {
            float* op = (mat == 0) ? g_q : g_k;
            #pragma unroll
            for (int idx = tid; idx < 2048; idx += 256) {
                int d = idx & 63, j = idx >> 6;
                op[((size_t)(b * LL + l0 + j)) * DDIM + d] = os[d * 33 + j];
            }
        } else {
            #pragma unroll
            for (int idx = tid; idx < 2048; idx += 256) {
                int j = idx & 31, d = idx >> 5;
                g_vT[((size_t)(b * DDIM + d)) * LL + l0 + j] = os[d * 33 + j];
            }
        }
        __syncthreads();
    }
}

// ---------------- mma.sync tf32 flash attention + fused out-proj ------------
// smem (floats): sK [64][68] @0, sV [64][68] @4352, sP: warp w @ 8704+w*1088
// epilogue reuses all of it as zs[128][133].
#define SMEM_FLOATS 17408
__global__ __launch_bounds__(256, 2) void attn_kernel(
    const float* __restrict__ inpt,
    const float* __restrict__ Wo,
    const float* __restrict__ bo,
    float* __restrict__ out)
{
    extern __shared__ float sm[];
    float* sK = sm;
    float* sV = sm + 4352;
    const int tid = threadIdx.x, w = tid >> 5, lane = tid & 31;
    const int bb = blockIdx.y, r0 = blockIdx.x * BM;
    const int qr = lane >> 2, qc = lane & 3;
    float* sPw = sm + 8704 + w * 1088;   // [16][68]
    const float SCALE = 0.18033688011112042f;   // log2(e)/8

    // stage this warp's Q rows (16 x 64) then load A-frags
    {
        const float* qsrc = g_q + ((size_t)(bb * LL + r0 + w * 16)) * DDIM;
        #pragma unroll
        for (int j = 0; j < 8; j++) {
            int idx = lane + j * 32;
            int row = idx >> 4, f4 = idx & 15;
            *(float4*)(sPw + row * 68 + f4 * 4) = ((const float4*)(qsrc + row * DDIM))[f4];
        }
    }
    __syncwarp();
    uint32_t qf[8][4];
    #pragma unroll
    for (int kk = 0; kk < 8; kk++) {
        qf[kk][0] = U(sPw[qr * 68 + kk * 8 + qc]);
        qf[kk][1] = U(sPw[(qr + 8) * 68 + kk * 8 + qc]);
        qf[kk][2] = U(sPw[qr * 68 + kk * 8 + qc + 4]);
        qf[kk][3] = U(sPw[(qr + 8) * 68 + kk * 8 + qc + 4]);
    }

    float o[8][4];
    #pragma unroll
    for (int i = 0; i < 8; i++) { o[i][0]=0.f; o[i][1]=0.f; o[i][2]=0.f; o[i][3]=0.f; }
    float slo = 0.f, shi = 0.f;

    for (int kt = 0; kt < NT; kt++) {
        __syncthreads();   // prior tile's sK/sV reads done
        {   // stage K [64 keys x 64] and VT [64 d x 64 keys]
            const float4* ks  = (const float4*)(g_k + ((size_t)(bb * LL + kt * BN)) * DDIM);
            const float*  vtb = g_vT + (size_t)bb * DDIM * LL + kt * BN;
            #pragma unroll
            for (int j = 0; j < 4; j++) {
                int idx = tid + j * 256;
                int row = idx >> 4, f4 = idx & 15;
                *(float4*)(sK + row * 68 + f4 * 4) = ks[row * 16 + f4];
                *(float4*)(sV + row * 68 + f4 * 4) =
                    *(const float4*)(vtb + (size_t)row * LL + f4 * 4);
            }
        }
        __syncthreads();

        // S = Q @ K^T  (16 x 64 per warp)
        float s[8][4];
        #pragma unroll
        for (int i = 0; i < 8; i++) { s[i][0]=0.f; s[i][1]=0.f; s[i][2]=0.f; s[i][3]=0.f; }
        #pragma unroll
        for (int kk = 0; kk < 8; kk++) {
            #pragma unroll
            for (int nb = 0; nb < 8; nb++) {
                uint32_t b0 = U(sK[(nb * 8 + qr) * 68 + kk * 8 + qc]);
                uint32_t b1 = U(sK[(nb * 8 + qr) * 68 + kk * 8 + qc + 4]);
                mma8(s[nb], qf[kk][0], qf[kk][1], qf[kk][2], qf[kk][3], b0, b1);
            }
        }

        __syncwarp();  // prior PV frag reads of sPw complete before overwrite
        // exp -> P (tf32) in per-warp smem
        #pragma unroll
        for (int nb = 0; nb < 8; nb++) {
            float p0 = to_tf32(fexp2_fast(s[nb][0] * SCALE));
            float p1 = to_tf32(fexp2_fast(s[nb][1] * SCALE));
            float p2 = to_tf32(fexp2_fast(s[nb][2] * SCALE));
            float p3 = to_tf32(fexp2_fast(s[nb][3] * SCALE));
            slo += p0 + p1; shi += p2 + p3;
            *(float2*)(sPw + qr * 68 + nb * 8 + 2 * qc)       = make_float2(p0, p1);
            *(float2*)(sPw + (qr + 8) * 68 + nb * 8 + 2 * qc) = make_float2(p2, p3);
        }
        __syncwarp();

        // O += P @ V
        #pragma unroll
        for (int kk = 0; kk < 8; kk++) {
            uint32_t a0 = U(sPw[qr * 68 + kk * 8 + qc]);
            uint32_t a1 = U(sPw[(qr + 8) * 68 + kk * 8 + qc]);
            uint32_t a2 = U(sPw[qr * 68 + kk * 8 + qc + 4]);
            uint32_t a3 = U(sPw[(qr + 8) * 68 + kk * 8 + qc + 4]);
            #pragma unroll
            for (int nb = 0; nb < 8; nb++) {
                uint32_t b0 = U(sV[(nb * 8 + qr) * 68 + kk * 8 + qc]);
                uint32_t b1 = U(sV[(nb * 8 + qr) * 68 + kk * 8 + qc + 4]);
                mma8(o[nb], a0, a1, a2, a3, b0, b1);
            }
        }
    }

    // row sums across quad
    slo += __shfl_xor_sync(0xFFFFFFFFu, slo, 1);
    slo += __shfl_xor_sync(0xFFFFFFFFu, slo, 2);
    shi += __shfl_xor_sync(0xFFFFFFFFu, shi, 1);
    shi += __shfl_xor_sync(0xFFFFFFFFu, shi, 2);
    const float ilo = 1.f / slo, ihi = 1.f / shi;

    __syncthreads();   // all sK/sV reads done before Wo staging
    {   // stage tf32 Wo [128][64] into sK..sV region (stride 68)
        #pragma unroll
        for (int j = 0; j < 8; j++) {
            int idx = tid + j * 256;
            int row = idx >> 4, f4 = idx & 15;
            float4 v = ((const float4*)(Wo + row * DDIM))[f4];
            v.x = to_tf32(v.x); v.y = to_tf32(v.y);
            v.z = to_tf32(v.z); v.w = to_tf32(v.w);
            *(float4*)(sm + row * 68 + f4 * 4) = v;
        }
    }
    // normalized tf32 ctx into sPw
    #pragma unroll
    for (int nb = 0; nb < 8; nb++) {
        float c0 = to_tf32(o[nb][0] * ilo);
        float c1 = to_tf32(o[nb][1] * ilo);
        float c2 = to_tf32(o[nb][2] * ihi);
        float c3 = to_tf32(o[nb][3] * ihi);
        *(float2*)(sPw + qr * 68 + nb * 8 + 2 * qc)       = make_float2(c0, c1);
        *(float2*)(sPw + (qr + 8) * 68 + nb * 8 + 2 * qc) = make_float2(c2, c3);
    }
    __syncthreads();

    // Z = ctx @ Wo^T : 16 rows x 128 cols per warp
    float z[16][4];
    #pragma unroll
    for (int i = 0; i < 16; i++) { z[i][0]=0.f; z[i][1]=0.f; z[i][2]=0.f; z[i][3]=0.f; }
    #pragma unroll
    for (int kk = 0; kk < 8; kk++) {
        uint32_t a0 = U(sPw[qr * 68 + kk * 8 + qc]);
        uint32_t a1 = U(sPw[(qr + 8) * 68 + kk * 8 + qc]);
        uint32_t a2 = U(sPw[qr * 68 + kk * 8 + qc + 4]);
        uint32_t a3 = U(sPw[(qr + 8) * 68 + kk * 8 + qc + 4]);
        #pragma unroll
        for (int nb = 0; nb < 16; nb++) {
            uint32_t b0 = U(sm[(nb * 8 + qr) * 68 + kk * 8 + qc]);
            uint32_t b1 = U(sm[(nb * 8 + qr) * 68 + kk * 8 + qc + 4]);
            mma8(z[nb], a0, a1, a2, a3, b0, b1);
        }
    }
    __syncthreads();   // done reading sW/sP before zs overwrite

    // stage Z into zs[128][133], then coalesced bias+residual store
    float* zs = sm;
    #pragma unroll
    for (int nb = 0; nb < 16; nb++) {
        int c = nb * 8 + 2 * qc;
        zs[(w * 16 + qr) * 133 + c]         = z[nb][0];
        zs[(w * 16 + qr) * 133 + c + 1]     = z[nb][1];
        zs[(w * 16 + qr + 8) * 133 + c]     = z[nb][2];
        zs[(w * 16 + qr + 8) * 133 + c + 1] = z[nb][3];
    }
    __syncthreads();

    const int row = tid & 127, chalf = tid >> 7;
    #pragma unroll 4
    for (int i = 0; i < 64; i++) {
        int c = i * 2 + chalf;
        size_t idx = ((size_t)(bb * CCH + c)) * LL + r0 + row;
        out[idx] = inpt[idx] + bo[c] + zs[row * 133 + c];
    }
}

extern "C" void kernel_launch(void* const* d_in, const int* in_sizes, int n_in,
                              void* d_out, int out_size)
{
    const float* inpt = (const float*)d_in[0];
    const float* Wq = (const float*)d_in[1];
    const float* bq = (const float*)d_in[2];
    const float* Wk = (const float*)d_in[3];
    const float* bk = (const float*)d_in[4];
    const float* Wv = (const float*)d_in[5];
    const float* bv = (const float*)d_in[6];
    const float* Wo = (const float*)d_in[7];
    const float* bo = (const float*)d_in[8];
    float* out = (float*)d_out;

    cudaFuncSetAttribute(attn_kernel, cudaFuncAttributeMaxDynamicSharedMemorySize,
                         SMEM_FLOATS * sizeof(float));

    dim3 g1(LL / 32, BSZ);
    qkv_kernel<<<g1, 256>>>(inpt, Wq, bq, Wk, bk, Wv, bv);
    dim3 g2(LL / BM, BSZ);
    attn_kernel<<<g2, 256, SMEM_FLOATS * sizeof(float)>>>(inpt, Wo, bo, out);
}

// round 6
// speedup vs baseline: 5.8228x; 2.0957x over previous
#include <cuda_runtime.h>
#include <cuda_bf16.h>
#include <cstdint>

#define BSZ 4
#define CCH 128
#define LL  4096
#define DDIM 64
#define BM  64
#define BN  64
#define NT  (LL/BN)

// bf16 q/k (token-major) and vT (d-major), stored as packed uint32 (bf16x2)
__device__ uint32_t g_q [BSZ * LL * 32];
__device__ uint32_t g_k [BSZ * LL * 32];
__device__ uint32_t g_vT[BSZ * DDIM * (LL/2)];

__device__ __forceinline__ uint32_t pack_bf16(float lo, float hi) {
    uint32_t r;
    asm("cvt.rn.bf16x2.f32 %0, %1, %2;" : "=r"(r) : "f"(hi), "f"(lo));
    return r;
}
__device__ __forceinline__ uint32_t smem_u32(const void* p) {
    uint32_t a;
    asm("{ .reg .u64 t; cvta.to.shared.u64 t, %1; cvt.u32.u64 %0, t; }" : "=r"(a) : "l"(p));
    return a;
}
__device__ __forceinline__ float fexp2_fast(float y) {
    float z = __fadd_rn(y, 12582912.f);
    int   n = __float_as_int(z);
    float t = __fsub_rn(z, 12582912.f);
    float f = __fsub_rn(y, t);
    float p = 1.3333558146e-3f;
    p = fmaf(p, f, 9.6181291918e-3f);
    p = fmaf(p, f, 5.5504108665e-2f);
    p = fmaf(p, f, 2.4022650696e-1f);
    p = fmaf(p, f, 6.9314718056e-1f);
    p = fmaf(p, f, 1.0f);
    return __int_as_float(__float_as_int(p) + (n << 23));
}
__device__ __forceinline__ void mma16(float* c,
    uint32_t a0, uint32_t a1, uint32_t a2, uint32_t a3, uint32_t b0, uint32_t b1)
{
    asm volatile("mma.sync.aligned.m16n8k16.row.col.f32.bf16.bf16.f32 "
        "{%0,%1,%2,%3}, {%4,%5,%6,%7}, {%8,%9}, {%0,%1,%2,%3};"
        : "+f"(c[0]), "+f"(c[1]), "+f"(c[2]), "+f"(c[3])
        : "r"(a0), "r"(a1), "r"(a2), "r"(a3), "r"(b0), "r"(b1));
}
__device__ __forceinline__ void cp16(uint32_t dst, const void* src) {
    asm volatile("cp.async.cg.shared.global [%0], [%1], 16;"
                 :: "r"(dst), "l"(src) : "memory");
}

// ---------------- QKV projection (FFMA, bf16 outputs; v transposed) ---------
__global__ __launch_bounds__(256) void qkv_kernel(
    const float* __restrict__ inpt,
    const float* __restrict__ Wq, const float* __restrict__ bq,
    const float* __restrict__ Wk, const float* __restrict__ bk,
    const float* __restrict__ Wv, const float* __restrict__ bv)
{
    __shared__ float xs[CCH * 33];
    __shared__ float os[DDIM * 33];
    const int b = blockIdx.y, l0 = blockIdx.x * 32, tid = threadIdx.x;

    const float* src = inpt + ((size_t)b * CCH) * LL + l0;
    #pragma unroll
    for (int idx = tid; idx < CCH * 32; idx += 256) {
        int c = idx >> 5, j = idx & 31;
        xs[c * 33 + j] = src[(size_t)c * LL + j];
    }
    __syncthreads();

    const float* Ws[3]  = {Wq, Wk, Wv};
    const float* bs_[3] = {bq, bk, bv};

    for (int mat = 0; mat < 3; mat++) {
        const float* __restrict__ Wp = Ws[mat];
        const float* __restrict__ bp = bs_[mat];
        float accs[8];
        #pragma unroll
        for (int k = 0; k < 8; k++) {
            int o = tid + k * 256;
            int j = o & 31, d = o >> 5;
            float a0 = bp[d], a1 = 0.f, a2 = 0.f, a3 = 0.f;
            const float4* w4 = (const float4*)(Wp + d * CCH);
            #pragma unroll
            for (int c4 = 0; c4 < CCH / 4; c4++) {
                float4 w = w4[c4];
                int c = c4 * 4;
                a0 += xs[(c + 0) * 33 + j] * w.x;
                a1 += xs[(c + 1) * 33 + j] * w.y;
                a2 += xs[(c + 2) * 33 + j] * w.z;
                a3 += xs[(c + 3) * 33 + j] * w.w;
            }
            accs[k] = (a0 + a1) + (a2 + a3);
        }
        __syncthreads();
        #pragma unroll
        for (int k = 0; k < 8; k++) {
            int o = tid + k * 256;
            os[(o >> 5) * 33 + (o & 31)] = accs[k];
        }
        __syncthreads();
        if (mat < 2) {
            uint32_t* op = (mat == 0) ? g_q : g_k;
            #pragma unroll
            for (int idx = tid; idx < 1024; idx += 256) {
                int d2 = idx & 31, j = idx >> 5;
                op[((size_t)(b * LL + l0 + j)) * 32 + d2] =
                    pack_bf16(os[(2 * d2) * 33 + j], os[(2 * d2 + 1) * 33 + j]);
            }
        } else {
            #pragma unroll
            for (int idx = tid; idx < 1024; idx += 256) {
                int d = idx & 63, jp = idx >> 6;  // jp 0..15
                g_vT[((size_t)(b * DDIM + d)) * (LL / 2) + (l0 >> 1) + jp] =
                    pack_bf16(os[d * 33 + 2 * jp], os[d * 33 + 2 * jp + 1]);
            }
        }
        __syncthreads();
    }
}

// ---------------- bf16 mma flash attention + fused out-proj -----------------
// K/V rows padded to 72 bf16 = 144B (conflict-free frag LDS).
#define RB 144
#define B_Q  0
#define B_K0 9216
#define B_K1 18432
#define B_V0 27648
#define B_V1 36864
#define B_WO 46080
#define B_LS 64512
#define B_O0 B_K0
#define B_O1 (B_K0 + 17408)
#define B_ZS B_K0
#define SMEM_BYTES 65024

__global__ __launch_bounds__(256, 2) void attn_kernel(
    const float* __restrict__ inpt,
    const float* __restrict__ Wo,
    const float* __restrict__ bo,
    float* __restrict__ out)
{
    extern __shared__ char sm[];
    const uint32_t sb = smem_u32(sm);
    const int tid = threadIdx.x, w = tid >> 5, lane = tid & 31;
    const int wr = w & 3, wc = w >> 2;        // row-group / key-half
    const int g = lane >> 2, qd = lane & 3;
    const int bb = blockIdx.y, r0 = blockIdx.x * BM;
    const float SCALE = 0.18033688011112042f; // log2(e)/8

    // stage Q (64 rows x 128B)
    {
        const uint4* qs = (const uint4*)(g_q + ((size_t)(bb * LL + r0)) * 32);
        #pragma unroll
        for (int i = 0; i < 2; i++) {
            int idx = tid + i * 256, row = idx >> 3, ch = idx & 7;
            *(uint4*)(sm + B_Q + row * RB + ch * 16) = qs[row * 8 + ch];
        }
    }
    // stage Wo as bf16 (128 rows x 64)
    {
        #pragma unroll
        for (int i = 0; i < 16; i++) {
            int idx = tid + i * 256, c = idx >> 5, dp = idx & 31;
            float2 v = *(const float2*)(Wo + c * DDIM + dp * 2);
            *(uint32_t*)(sm + B_WO + c * RB + dp * 4) = pack_bf16(v.x, v.y);
        }
    }
    // stage K/V tile 0 (cp.async)
    {
        const uint32_t* ks = g_k + ((size_t)(bb * LL)) * 32;
        const uint32_t* vs = g_vT + ((size_t)(bb * DDIM)) * (LL / 2);
        #pragma unroll
        for (int i = 0; i < 2; i++) {
            int idx = tid + i * 256, row = idx >> 3, ch = idx & 7;
            cp16(sb + B_K0 + row * RB + ch * 16, ks + (size_t)row * 32 + ch * 4);
            cp16(sb + B_V0 + row * RB + ch * 16, vs + (size_t)row * (LL / 2) + ch * 4);
        }
        asm volatile("cp.async.commit_group;" ::: "memory");
    }
    __syncthreads();

    // Q A-frags (4 k-steps)
    uint32_t qf[4][4];
    #pragma unroll
    for (int kk = 0; kk < 4; kk++) {
        int rbase = B_Q + (wr * 16 + g) * RB + kk * 32 + qd * 4;
        qf[kk][0] = *(uint32_t*)(sm + rbase);
        qf[kk][1] = *(uint32_t*)(sm + rbase + 8 * RB);
        qf[kk][2] = *(uint32_t*)(sm + rbase + 16);
        qf[kk][3] = *(uint32_t*)(sm + rbase + 8 * RB + 16);
    }

    float o[8][4];
    #pragma unroll
    for (int i = 0; i < 8; i++) { o[i][0]=0.f; o[i][1]=0.f; o[i][2]=0.f; o[i][3]=0.f; }
    float slo = 0.f, shi = 0.f;

    for (int kt = 0; kt < NT; kt++) {
        if (kt + 1 < NT) {   // prefetch next tile
            int kb = (kt + 1) & 1;
            const uint32_t* ks = g_k + ((size_t)(bb * LL + (kt + 1) * BN)) * 32;
            const uint32_t* vs = g_vT + ((size_t)(bb * DDIM)) * (LL / 2) + (kt + 1) * 32;
            #pragma unroll
            for (int i = 0; i < 2; i++) {
                int idx = tid + i * 256, row = idx >> 3, ch = idx & 7;
                cp16(sb + (kb ? B_K1 : B_K0) + row * RB + ch * 16,
                     ks + (size_t)row * 32 + ch * 4);
                cp16(sb + (kb ? B_V1 : B_V0) + row * RB + ch * 16,
                     vs + (size_t)row * (LL / 2) + ch * 4);
            }
            asm volatile("cp.async.commit_group;" ::: "memory");
            asm volatile("cp.async.wait_group 1;" ::: "memory");
        } else {
            asm volatile("cp.async.wait_group 0;" ::: "memory");
        }
        __syncthreads();

        const char* bK = sm + ((kt & 1) ? B_K1 : B_K0);
        const char* bV = sm + ((kt & 1) ? B_V1 : B_V0);

        // S = Q @ K^T  (16 rows x 32 keys per warp)
        float s[4][4];
        #pragma unroll
        for (int i = 0; i < 4; i++) { s[i][0]=0.f; s[i][1]=0.f; s[i][2]=0.f; s[i][3]=0.f; }
        #pragma unroll
        for (int kk = 0; kk < 4; kk++) {
            #pragma unroll
            for (int nb = 0; nb < 4; nb++) {
                int kr = (wc * 32 + nb * 8 + g) * RB + kk * 32 + qd * 4;
                uint32_t b0 = *(const uint32_t*)(bK + kr);
                uint32_t b1 = *(const uint32_t*)(bK + kr + 16);
                mma16(s[nb], qf[kk][0], qf[kk][1], qf[kk][2], qf[kk][3], b0, b1);
            }
        }

        // exp -> bf16x2 P frags (C-frag pairs ARE A-frag pairs for k16)
        uint32_t pr[4][2];
        #pragma unroll
        for (int nb = 0; nb < 4; nb++) {
            float p0 = fexp2_fast(s[nb][0] * SCALE);
            float p1 = fexp2_fast(s[nb][1] * SCALE);
            float p2 = fexp2_fast(s[nb][2] * SCALE);
            float p3 = fexp2_fast(s[nb][3] * SCALE);
            slo += p0 + p1; shi += p2 + p3;
            pr[nb][0] = pack_bf16(p0, p1);
            pr[nb][1] = pack_bf16(p2, p3);
        }

        // O += P @ V (d = 64 cols, keys = warp's 32)
        #pragma unroll
        for (int j = 0; j < 2; j++) {
            uint32_t a0 = pr[2*j][0], a1 = pr[2*j][1];
            uint32_t a2 = pr[2*j+1][0], a3 = pr[2*j+1][1];
            #pragma unroll
            for (int nb = 0; nb < 8; nb++) {
                int vr = (nb * 8 + g) * RB + wc * 64 + j * 32 + qd * 4;
                uint32_t b0 = *(const uint32_t*)(bV + vr);
                uint32_t b1 = *(const uint32_t*)(bV + vr + 16);
                mma16(o[nb], a0, a1, a2, a3, b0, b1);
            }
        }
        __syncthreads();   // done reading this buffer before it is re-staged
    }

    // quad-reduce row sums, publish per key-half
    slo += __shfl_xor_sync(0xFFFFFFFFu, slo, 1);
    slo += __shfl_xor_sync(0xFFFFFFFFu, slo, 2);
    shi += __shfl_xor_sync(0xFFFFFFFFu, shi, 1);
    shi += __shfl_xor_sync(0xFFFFFFFFu, shi, 2);
    if (qd == 0) {
        *(float*)(sm + B_LS + (wc * 64 + wr * 16 + g) * 4) = slo;
        *(float*)(sm + B_LS + (wc * 64 + wr * 16 + g + 8) * 4) = shi;
    }
    // partial O to smem (per key-half buffer)
    {
        float* sO = (float*)(sm + (wc ? B_O1 : B_O0));
        #pragma unroll
        for (int nb = 0; nb < 8; nb++) {
            int row0 = wr * 16 + g, d = nb * 8 + qd * 2;
            *(float2*)(sO + row0 * 68 + d)       = make_float2(o[nb][0], o[nb][1]);
            *(float2*)(sO + (row0 + 8) * 68 + d) = make_float2(o[nb][2], o[nb][3]);
        }
    }
    __syncthreads();

    // combine halves, normalize, bf16 ctx into B_Q
    {
        const float* ls = (const float*)(sm + B_LS);
        const float* O0 = (const float*)(sm + B_O0);
        const float* O1 = (const float*)(sm + B_O1);
        int row = tid >> 2, dq = (tid & 3) * 16;
        float invl = 1.f / (ls[row] + ls[64 + row]);
        #pragma unroll
        for (int i = 0; i < 8; i++) {
            int d = dq + 2 * i;
            float c0 = (O0[row * 68 + d] + O1[row * 68 + d]) * invl;
            float c1 = (O0[row * 68 + d + 1] + O1[row * 68 + d + 1]) * invl;
            *(uint32_t*)(sm + B_Q + row * RB + d * 2) = pack_bf16(c0, c1);
        }
    }
    __syncthreads();

    // Z = ctx @ Wo^T (16 rows x 64 cols per warp)
    float z[8][4];
    #pragma unroll
    for (int i = 0; i < 8; i++) { z[i][0]=0.f; z[i][1]=0.f; z[i][2]=0.f; z[i][3]=0.f; }
    #pragma unroll
    for (int kk = 0; kk < 4; kk++) {
        int rbase = B_Q + (wr * 16 + g) * RB + kk * 32 + qd * 4;
        uint32_t a0 = *(uint32_t*)(sm + rbase);
        uint32_t a1 = *(uint32_t*)(sm + rbase + 8 * RB);
        uint32_t a2 = *(uint32_t*)(sm + rbase + 16);
        uint32_t a3 = *(uint32_t*)(sm + rbase + 8 * RB + 16);
        #pragma unroll
        for (int nb = 0; nb < 8; nb++) {
            int cr = B_WO + (wc * 64 + nb * 8 + g) * RB + kk * 32 + qd * 4;
            uint32_t b0 = *(uint32_t*)(sm + cr);
            uint32_t b1 = *(uint32_t*)(sm + cr + 16);
            mma16(z[nb], a0, a1, a2, a3, b0, b1);
        }
    }
    __syncthreads();   // O0/O1 reads finished before zs overwrite

    // stage Z (stride 133 = conflict-free reads), then coalesced store
    {
        float* zs = (float*)(sm + B_ZS);
        #pragma unroll
        for (int nb = 0; nb < 8; nb++) {
            int c = wc * 64 + nb * 8 + qd * 2, row0 = wr * 16 + g;
            zs[row0 * 133 + c]           = z[nb][0];
            zs[row0 * 133 + c + 1]       = z[nb][1];
            zs[(row0 + 8) * 133 + c]     = z[nb][2];
            zs[(row0 + 8) * 133 + c + 1] = z[nb][3];
        }
    }
    __syncthreads();
    {
        const float* zs = (const float*)(sm + B_ZS);
        int srow = tid & 63, cbase = (tid >> 6) * 32;
        #pragma unroll 8
        for (int i = 0; i < 32; i++) {
            int c = cbase + i;
            size_t idx = ((size_t)(bb * CCH + c)) * LL + r0 + srow;
            out[idx] = inpt[idx] + bo[c] + zs[srow * 133 + c];
        }
    }
}

extern "C" void kernel_launch(void* const* d_in, const int* in_sizes, int n_in,
                              void* d_out, int out_size)
{
    const float* inpt = (const float*)d_in[0];
    const float* Wq = (const float*)d_in[1];
    const float* bq = (const float*)d_in[2];
    const float* Wk = (const float*)d_in[3];
    const float* bk = (const float*)d_in[4];
    const float* Wv = (const float*)d_in[5];
    const float* bv = (const float*)d_in[6];
    const float* Wo = (const float*)d_in[7];
    const float* bo = (const float*)d_in[8];
    float* out = (float*)d_out;

    cudaFuncSetAttribute(attn_kernel, cudaFuncAttributeMaxDynamicSharedMemorySize,
                         SMEM_BYTES);

    dim3 g1(LL / 32, BSZ);
    qkv_kernel<<<g1, 256>>>(inpt, Wq, bq, Wk, bk, Wv, bv);
    dim3 g2(LL / BM, BSZ);
    attn_kernel<<<g2, 256, SMEM_BYTES>>>(inpt, Wo, bo, out);
}

// round 8
// speedup vs baseline: 11.4057x; 1.9588x over previous
#include <cuda_runtime.h>
#include <cuda_bf16.h>
#include <cstdint>

#define BSZ 4
#define CCH 128
#define LL  4096
#define DDIM 64
#define BM  64
#define BN  64
#define NT  (LL/BN)

// bf16 q/k/v, all token-major, packed bf16x2 (d-pairs)
__device__ uint32_t g_q[BSZ * LL * 32];
__device__ uint32_t g_k[BSZ * LL * 32];
__device__ uint32_t g_v[BSZ * LL * 32];

__device__ __forceinline__ uint32_t pack_bf16(float lo, float hi) {
    uint32_t r;
    asm("cvt.rn.bf16x2.f32 %0, %1, %2;" : "=r"(r) : "f"(hi), "f"(lo));
    return r;
}
__device__ __forceinline__ uint32_t smem_u32(const void* p) {
    uint32_t a;
    asm("{ .reg .u64 t; cvta.to.shared.u64 t, %1; cvt.u32.u64 %0, t; }" : "=r"(a) : "l"(p));
    return a;
}
__device__ __forceinline__ float ex2f(float x) {
    float r; asm("ex2.approx.f32 %0, %1;" : "=f"(r) : "f"(x)); return r;
}
__device__ __forceinline__ void mma16(float* c,
    uint32_t a0, uint32_t a1, uint32_t a2, uint32_t a3, uint32_t b0, uint32_t b1)
{
    asm volatile("mma.sync.aligned.m16n8k16.row.col.f32.bf16.bf16.f32 "
        "{%0,%1,%2,%3}, {%4,%5,%6,%7}, {%8,%9}, {%0,%1,%2,%3};"
        : "+f"(c[0]), "+f"(c[1]), "+f"(c[2]), "+f"(c[3])
        : "r"(a0), "r"(a1), "r"(a2), "r"(a3), "r"(b0), "r"(b1));
}
__device__ __forceinline__ void ldm4(uint32_t* r, uint32_t addr) {
    asm volatile("ldmatrix.sync.aligned.m8n8.x4.shared.b16 {%0,%1,%2,%3}, [%4];"
        : "=r"(r[0]), "=r"(r[1]), "=r"(r[2]), "=r"(r[3]) : "r"(addr));
}
__device__ __forceinline__ void ldm4t(uint32_t* r, uint32_t addr) {
    asm volatile("ldmatrix.sync.aligned.m8n8.x4.trans.shared.b16 {%0,%1,%2,%3}, [%4];"
        : "=r"(r[0]), "=r"(r[1]), "=r"(r[2]), "=r"(r[3]) : "r"(addr));
}
__device__ __forceinline__ void cp16(uint32_t dst, const void* src) {
    asm volatile("cp.async.cg.shared.global [%0], [%1], 16;"
                 :: "r"(dst), "l"(src) : "memory");
}
#define CP_COMMIT() asm volatile("cp.async.commit_group;" ::: "memory")

// =================== QKV via bf16 mma (x split hi+lo) =======================
#define XR 272                 // row stride bytes (136 bf16)
#define SW_W   0               // 192*272 = 52224
#define SW_B   52224           // 192 floats
#define SW_XH  52992           // 64*272
#define SW_XL  70400           // 64*272
#define SW_X32 87808           // 64*68*4 = 17408 (fp32 stage, half tile)
#define QKV_SMEM 105216

__global__ __launch_bounds__(256, 2) void qkv_kernel(
    const float* __restrict__ inpt,
    const float* __restrict__ Wq, const float* __restrict__ bq,
    const float* __restrict__ Wk, const float* __restrict__ bk,
    const float* __restrict__ Wv, const float* __restrict__ bv)
{
    extern __shared__ char sq[];
    const uint32_t sb = smem_u32(sq);
    const int tid = threadIdx.x, w = tid >> 5, lane = tid & 31;
    const int g = lane >> 2, qd = lane & 3;
    const int wr = w & 3, wc = w >> 2;       // M-block (16 rows), N-half (96)
    const int b = blockIdx.y, l0 = blockIdx.x * 64;

    // stage W (192 rows x 128 c) as bf16, + bias
    {
        const float* Wsrc[3] = {Wq, Wk, Wv};
        #pragma unroll
        for (int i = 0; i < 24; i++) {
            int idx = tid + i * 256;           // 0..6143
            int r = idx >> 5, c4 = idx & 31;
            const float4 v = *(const float4*)(Wsrc[r >> 6] + (r & 63) * CCH + c4 * 4);
            *(uint2*)(sq + SW_W + r * XR + c4 * 8) =
                make_uint2(pack_bf16(v.x, v.y), pack_bf16(v.z, v.w));
        }
        if (tid < 192) {
            const float* bsrc[3] = {bq, bk, bv};
            ((float*)(sq + SW_B))[tid] = bsrc[tid >> 6][tid & 63];
        }
    }

    // stage x in 2 c-halves -> xhi/xlo [64 tokens][128 c]
    #pragma unroll
    for (int h = 0; h < 2; h++) {
        __syncthreads();
        const float* src = inpt + ((size_t)b * CCH + h * 64) * LL + l0;
        #pragma unroll
        for (int i = 0; i < 4; i++) {
            int idx = tid + i * 256;            // 0..1023
            int c = idx >> 4, j4 = idx & 15;
            *(float4*)(sq + SW_X32 + (c * 68 + j4 * 4) * 4) =
                *(const float4*)(src + (size_t)c * LL + j4 * 4);
        }
        __syncthreads();
        const int j = tid & 63, q4 = tid >> 6;  // 16 c's per thread
        const float* x32 = (const float*)(sq + SW_X32);
        uint32_t hi[8], lo[8];
        #pragma unroll
        for (int i2 = 0; i2 < 8; i2++) {
            float a  = x32[(q4 * 16 + 2 * i2) * 68 + j];
            float b2 = x32[(q4 * 16 + 2 * i2 + 1) * 68 + j];
            hi[i2] = pack_bf16(a, b2);
            float ah = __bfloat162float(__float2bfloat16(a));
            float bh = __bfloat162float(__float2bfloat16(b2));
            lo[i2] = pack_bf16(a - ah, b2 - bh);
        }
        int off = j * XR + h * 128 + q4 * 32;
        *(uint4*)(sq + SW_XH + off)      = make_uint4(hi[0], hi[1], hi[2], hi[3]);
        *(uint4*)(sq + SW_XH + off + 16) = make_uint4(hi[4], hi[5], hi[6], hi[7]);
        *(uint4*)(sq + SW_XL + off)      = make_uint4(lo[0], lo[1], lo[2], lo[3]);
        *(uint4*)(sq + SW_XL + off + 16) = make_uint4(lo[4], lo[5], lo[6], lo[7]);
    }
    __syncthreads();

    // mma: acc[12 n-blocks][4]
    float acc[12][4];
    #pragma unroll
    for (int i = 0; i < 12; i++) { acc[i][0]=0.f; acc[i][1]=0.f; acc[i][2]=0.f; acc[i][3]=0.f; }

    const uint32_t arow = (uint32_t)(wr * 16 + ((lane >> 3) & 1) * 8 + (lane & 7));
    const uint32_t brow = (uint32_t)(wc * 96 + (lane >> 4) * 8 + (lane & 7));
    #pragma unroll
    for (int kk = 0; kk < 8; kk++) {
        uint32_t ah[4], al[4], bw[6][4];
        uint32_t aaddr = sb + SW_XH + arow * XR + kk * 32 + (lane >> 4) * 16;
        ldm4(ah, aaddr);
        ldm4(al, aaddr + (SW_XL - SW_XH));
        #pragma unroll
        for (int hh = 0; hh < 6; hh++)
            ldm4(bw[hh], sb + SW_W + (brow + hh * 16) * XR + kk * 32 + ((lane >> 3) & 1) * 16);
        #pragma unroll
        for (int nb = 0; nb < 12; nb++) {
            uint32_t b0 = bw[nb >> 1][(nb & 1) * 2], b1 = bw[nb >> 1][(nb & 1) * 2 + 1];
            mma16(acc[nb], ah[0], ah[1], ah[2], ah[3], b0, b1);
            mma16(acc[nb], al[0], al[1], al[2], al[3], b0, b1);
        }
    }

    // epilogue: +bias, pack bf16, store token-major
    {
        const float* bias = (const float*)(sq + SW_B);
        uint32_t* outs[3] = {g_q, g_k, g_v};
        const int token0 = l0 + wr * 16 + g;
        #pragma unroll
        for (int nb = 0; nb < 12; nb++) {
            int n = wc * 96 + nb * 8 + 2 * qd;
            float2 bb = *(const float2*)(bias + n);
            uint32_t* op = outs[n >> 6];
            int d = n & 63;
            size_t base = ((size_t)(b * LL + token0)) * 32 + (d >> 1);
            op[base]          = pack_bf16(acc[nb][0] + bb.x, acc[nb][1] + bb.y);
            op[base + 8 * 32] = pack_bf16(acc[nb][2] + bb.x, acc[nb][3] + bb.y);
        }
    }
}

// =================== attention + fused out-proj =============================
#define RB 144
#define A_Q   0
#define A_KVB 9216            // 3 bufs of (K 9216 + V 9216)
#define A_WO  64512           // 128*144
#define A_LS  82944
#define A_O0  9216
#define A_O1  26624
#define A_ZS  9216
#define ASMEM 83456

__global__ __launch_bounds__(256, 2) void attn_kernel(
    const float* __restrict__ inpt,
    const float* __restrict__ Wo,
    const float* __restrict__ bo,
    float* __restrict__ out)
{
    extern __shared__ char sm[];
    const uint32_t sb = smem_u32(sm);
    const int tid = threadIdx.x, w = tid >> 5, lane = tid & 31;
    const int wr = w & 3, wc = w >> 2;        // row-group / key-half
    const int g = lane >> 2, qd = lane & 3;
    const int bb = blockIdx.y, r0 = blockIdx.x * BM;
    const float SCALE = 0.18033688011112042f; // log2(e)/8

    // stage Q (64 rows x 64 bf16 = 128B/row) : 512 chunks of 16B
    {
        #pragma unroll
        for (int i = 0; i < 2; i++) {
            int idx = tid + i * 256, row = idx >> 3, ch = idx & 7;
            *(uint4*)(sm + A_Q + row * RB + ch * 16) =
                *(const uint4*)(g_q + ((size_t)(bb * LL + r0 + row)) * 32 + ch * 4);
        }
    }
    // stage Wo bf16 (128 rows x 64) : 1024 chunks (8 floats -> 16B)
    {
        #pragma unroll
        for (int i = 0; i < 4; i++) {
            int idx = tid + i * 256, row = idx >> 3, ch = idx & 7;
            const float4 v0 = *(const float4*)(Wo + row * DDIM + ch * 8);
            const float4 v1 = *(const float4*)(Wo + row * DDIM + ch * 8 + 4);
            *(uint4*)(sm + A_WO + row * RB + ch * 16) =
                make_uint4(pack_bf16(v0.x, v0.y), pack_bf16(v0.z, v0.w),
                           pack_bf16(v1.x, v1.y), pack_bf16(v1.z, v1.w));
        }
    }
    // prologue KV stage -> buf 0
    {
        int row = tid >> 2, ch = tid & 3;
        const uint32_t* ks = g_k + ((size_t)(bb * LL)) * 32;
        const uint32_t* vs = g_v + ((size_t)(bb * LL)) * 32;
        #pragma unroll
        for (int i = 0; i < 2; i++) {
            cp16(sb + A_KVB + row * RB + (ch + 4 * i) * 16, ks + (size_t)row * 32 + (ch + 4 * i) * 4);
            cp16(sb + A_KVB + 9216 + row * RB + (ch + 4 * i) * 16, vs + (size_t)row * 32 + (ch + 4 * i) * 4);
        }
        CP_COMMIT();
    }
    __syncthreads();

    // Q frags
    uint32_t qf[4][4];
    {
        uint32_t qrow = (uint32_t)(wr * 16 + ((lane >> 3) & 1) * 8 + (lane & 7));
        #pragma unroll
        for (int kk = 0; kk < 4; kk++)
            ldm4(qf[kk], sb + A_Q + qrow * RB + kk * 32 + (lane >> 4) * 16);
    }

    float o[8][4];
    #pragma unroll
    for (int i = 0; i < 8; i++) { o[i][0]=0.f; o[i][1]=0.f; o[i][2]=0.f; o[i][3]=0.f; }
    float slo = 0.f, shi = 0.f;

    const uint32_t krow = (uint32_t)(wc * 32 + (lane >> 4) * 8 + (lane & 7)) * RB
                        + ((lane >> 3) & 1) * 16;   // + h*16*RB + kk*32
    const uint32_t vrow = (uint32_t)(wc * 32 + ((lane >> 3) & 1) * 8 + (lane & 7)) * RB
                        + (lane >> 4) * 16;         // + j*16*RB + hh*32

    for (int kt = 0; kt < NT; kt++) {
        if (kt + 1 < NT) {   // prefetch into buf (kt+1)%3
            uint32_t dst = sb + A_KVB + ((kt + 1) % 3) * 18432;
            int row = tid >> 2, ch = tid & 3;
            const uint32_t* ks = g_k + ((size_t)(bb * LL + (kt + 1) * BN)) * 32;
            const uint32_t* vs = g_v + ((size_t)(bb * LL + (kt + 1) * BN)) * 32;
            #pragma unroll
            for (int i = 0; i < 2; i++) {
                cp16(dst + row * RB + (ch + 4 * i) * 16, ks + (size_t)row * 32 + (ch + 4 * i) * 4);
                cp16(dst + 9216 + row * RB + (ch + 4 * i) * 16, vs + (size_t)row * 32 + (ch + 4 * i) * 4);
            }
            CP_COMMIT();
            asm volatile("cp.async.wait_group 1;" ::: "memory");
        } else {
            asm volatile("cp.async.wait_group 0;" ::: "memory");
        }
        __syncthreads();

        const uint32_t bK = sb + A_KVB + (kt % 3) * 18432;
        const uint32_t bV = bK + 9216;

        // K frags: kf[kk][h][4]
        uint32_t kf[4][2][4];
        #pragma unroll
        for (int kk = 0; kk < 4; kk++)
            #pragma unroll
            for (int h = 0; h < 2; h++)
                ldm4(kf[kk][h], bK + krow + h * 16 * RB + kk * 32);

        // S = Q @ K^T
        float s[4][4];
        #pragma unroll
        for (int i = 0; i < 4; i++) { s[i][0]=0.f; s[i][1]=0.f; s[i][2]=0.f; s[i][3]=0.f; }
        #pragma unroll
        for (int kk = 0; kk < 4; kk++)
            #pragma unroll
            for (int nb = 0; nb < 4; nb++)
                mma16(s[nb], qf[kk][0], qf[kk][1], qf[kk][2], qf[kk][3],
                      kf[kk][nb >> 1][(nb & 1) * 2], kf[kk][nb >> 1][(nb & 1) * 2 + 1]);

        // exp via MUFU
        uint32_t pr[4][2];
        #pragma unroll
        for (int nb = 0; nb < 4; nb++) {
            float p0 = ex2f(s[nb][0] * SCALE);
            float p1 = ex2f(s[nb][1] * SCALE);
            float p2 = ex2f(s[nb][2] * SCALE);
            float p3 = ex2f(s[nb][3] * SCALE);
            slo += p0 + p1; shi += p2 + p3;
            pr[nb][0] = pack_bf16(p0, p1);
            pr[nb][1] = pack_bf16(p2, p3);
        }

        // V frags (trans): vf[j][hh][4]
        uint32_t vf[2][4][4];
        #pragma unroll
        for (int j = 0; j < 2; j++)
            #pragma unroll
            for (int hh = 0; hh < 4; hh++)
                ldm4t(vf[j][hh], bV + vrow + j * 16 * RB + hh * 32);

        // O += P @ V
        #pragma unroll
        for (int j = 0; j < 2; j++) {
            uint32_t a0 = pr[2*j][0], a1 = pr[2*j][1];
            uint32_t a2 = pr[2*j+1][0], a3 = pr[2*j+1][1];
            #pragma unroll
            for (int nb = 0; nb < 8; nb++)
                mma16(o[nb], a0, a1, a2, a3,
                      vf[j][nb >> 1][(nb & 1) * 2], vf[j][nb >> 1][(nb & 1) * 2 + 1]);
        }
    }
    __syncthreads();   // all KV-buffer reads done before O0/O1 aliasing writes

    // quad-reduce row sums, publish per key-half
    slo += __shfl_xor_sync(0xFFFFFFFFu, slo, 1);
    slo += __shfl_xor_sync(0xFFFFFFFFu, slo, 2);
    shi += __shfl_xor_sync(0xFFFFFFFFu, shi, 1);
    shi += __shfl_xor_sync(0xFFFFFFFFu, shi, 2);
    if (qd == 0) {
        *(float*)(sm + A_LS + (wc * 64 + wr * 16 + g) * 4) = slo;
        *(float*)(sm + A_LS + (wc * 64 + wr * 16 + g + 8) * 4) = shi;
    }
    // partial O per key-half
    {
        float* sO = (float*)(sm + (wc ? A_O1 : A_O0));
        #pragma unroll
        for (int nb = 0; nb < 8; nb++) {
            int row0 = wr * 16 + g, d = nb * 8 + qd * 2;
            *(float2*)(sO + row0 * 68 + d)       = make_float2(o[nb][0], o[nb][1]);
            *(float2*)(sO + (row0 + 8) * 68 + d) = make_float2(o[nb][2], o[nb][3]);
        }
    }
    __syncthreads();

    // combine halves, normalize, bf16 ctx into A_Q
    {
        const float* ls = (const float*)(sm + A_LS);
        const float* O0 = (const float*)(sm + A_O0);
        const float* O1 = (const float*)(sm + A_O1);
        int row = tid >> 2, dq = (tid & 3) * 16;
        float invl = 1.f / (ls[row] + ls[64 + row]);
        #pragma unroll
        for (int i = 0; i < 8; i++) {
            int d = dq + 2 * i;
            float c0 = (O0[row * 68 + d] + O1[row * 68 + d]) * invl;
            float c1 = (O0[row * 68 + d + 1] + O1[row * 68 + d + 1]) * invl;
            *(uint32_t*)(sm + A_Q + row * RB + d * 2) = pack_bf16(c0, c1);
        }
    }
    __syncthreads();

    // Z = ctx @ Wo^T
    float z[8][4];
    #pragma unroll
    for (int i = 0; i < 8; i++) { z[i][0]=0.f; z[i][1]=0.f; z[i][2]=0.f; z[i][3]=0.f; }
    {
        uint32_t qrow = (uint32_t)(wr * 16 + ((lane >> 3) & 1) * 8 + (lane & 7));
        uint32_t wrow = (uint32_t)(wc * 64 + (lane >> 4) * 8 + (lane & 7)) * RB
                      + ((lane >> 3) & 1) * 16;
        #pragma unroll
        for (int kk = 0; kk < 4; kk++) {
            uint32_t cf[4], wf[4][4];
            ldm4(cf, sb + A_Q + qrow * RB + kk * 32 + (lane >> 4) * 16);
            #pragma unroll
            for (int hh = 0; hh < 4; hh++)
                ldm4(wf[hh], sb + A_WO + wrow + hh * 16 * RB + kk * 32);
            #pragma unroll
            for (int nb = 0; nb < 8; nb++)
                mma16(z[nb], cf[0], cf[1], cf[2], cf[3],
                      wf[nb >> 1][(nb & 1) * 2], wf[nb >> 1][(nb & 1) * 2 + 1]);
        }
    }
    __syncthreads();

    // stage Z (stride 133), coalesced bias+residual store
    {
        float* zs = (float*)(sm + A_ZS);
        #pragma unroll
        for (int nb = 0; nb < 8; nb++) {
            int c = wc * 64 + nb * 8 + qd * 2, row0 = wr * 16 + g;
            zs[row0 * 133 + c]           = z[nb][0];
            zs[row0 * 133 + c + 1]       = z[nb][1];
            zs[(row0 + 8) * 133 + c]     = z[nb][2];
            zs[(row0 + 8) * 133 + c + 1] = z[nb][3];
        }
    }
    __syncthreads();
    {
        const float* zs = (const float*)(sm + A_ZS);
        int srow = tid & 63, cbase = (tid >> 6) * 32;
        #pragma unroll 8
        for (int i = 0; i < 32; i++) {
            int c = cbase + i;
            size_t idx = ((size_t)(bb * CCH + c)) * LL + r0 + srow;
            out[idx] = inpt[idx] + bo[c] + zs[srow * 133 + c];
        }
    }
}

extern "C" void kernel_launch(void* const* d_in, const int* in_sizes, int n_in,
                              void* d_out, int out_size)
{
    const float* inpt = (const float*)d_in[0];
    const float* Wq = (const float*)d_in[1];
    const float* bq = (const float*)d_in[2];
    const float* Wk = (const float*)d_in[3];
    const float* bk = (const float*)d_in[4];
    const float* Wv = (const float*)d_in[5];
    const float* bv = (const float*)d_in[6];
    const float* Wo = (const float*)d_in[7];
    const float* bo = (const float*)d_in[8];
    float* out = (float*)d_out;

    cudaFuncSetAttribute(qkv_kernel, cudaFuncAttributeMaxDynamicSharedMemorySize, QKV_SMEM);
    cudaFuncSetAttribute(attn_kernel, cudaFuncAttributeMaxDynamicSharedMemorySize, ASMEM);

    dim3 g1(LL / 64, BSZ);
    qkv_kernel<<<g1, 256, QKV_SMEM>>>(inpt, Wq, bq, Wk, bk, Wv, bv);
    dim3 g2(LL / BM, BSZ);
    attn_kernel<<<g2, 256, ASMEM>>>(inpt, Wo, bo, out);
}